// round 14
// baseline (speedup 1.0000x reference)
#include <cuda_runtime.h>
#include <cuda_fp16.h>
#include <math.h>

#define NN 50000
#define EE 800000
#define GG 256
#define NLAYERS 4
#define DEGCAP 96   // max in-degree capacity (Poisson(16): P(>=96) ~ e^-92, x50k nodes ~ 0)

// ---------------- static device scratch ----------------
__device__ __align__(16) float  d_h [NN * 64];
__device__ __align__(16) __half d_xp[NN * 64];   // fp16 messages
__device__ __align__(16) float  d_as[NN * 4];
__device__ __align__(16) float  d_ad[NN * 4];
__device__ int   d_cnt[NN];          // in-degree; reset by last gather each call
__device__ int   d_ell[NN * DEGCAP]; // ELL adjacency: src lists per dst
__device__ float d_w0[128 * 64];     // combined embed@gatW0 weight
__device__ float d_b0[64];           // combined embed bias through gatW0
__device__ float d_bn[128];          // kept zeroed between calls
__device__ float d_bnscale[64];
__device__ float d_bnshift[64];
__device__ float d_g [GG * 64];      // zeroed by last gather each call
__device__ unsigned int d_tick;      // last-block ticket (kept zeroed)

__device__ __forceinline__ float lrelu(float x) { return x > 0.0f ? x : 0.2f * x; }
__device__ __forceinline__ float elu(float x)   { return x > 0.0f ? x : expm1f(x); }

// ---------------- ELL build: one kernel, replaces hist/scan/scatter ----------------
__global__ void ell_scatter_kernel(const int* __restrict__ ei) {
    int i0 = (blockIdx.x * blockDim.x + threadIdx.x) * 2;
    if (i0 < EE) {
        int2 dd = *reinterpret_cast<const int2*>(&ei[EE + i0]);   // EE even -> aligned
        int2 ss = *reinterpret_cast<const int2*>(&ei[i0]);
        int p0 = atomicAdd(&d_cnt[dd.x], 1);
        int p1 = atomicAdd(&d_cnt[dd.y], 1);
        d_ell[dd.x * DEGCAP + p0] = ss.x;
        d_ell[dd.y * DEGCAP + p1] = ss.y;
    }
}

// ---------------- combine: W0' = embW @ gatW0, b0' = embB @ gatW0 ----------------
// 8 blocks x 256 threads; block b covers rows [16b, 16b+16)
__global__ void combine_kernel(const float* __restrict__ embW,
                               const float* __restrict__ embB,
                               const float* __restrict__ gatW0) {
    __shared__ float Wsh[64 * 64];
    int tid = threadIdx.x;
    for (int i = tid; i < 64 * 64; i += 256) Wsh[i] = gatW0[i];
    __syncthreads();
    int j = tid & 63;
    int r0 = blockIdx.x * 16 + (tid >> 6);
    #pragma unroll
    for (int m = 0; m < 4; m++) {
        int r = r0 + 4 * m;
        float acc = 0.0f;
        #pragma unroll 8
        for (int k = 0; k < 64; k++) acc = fmaf(__ldg(&embW[r * 64 + k]), Wsh[k * 64 + j], acc);
        d_w0[r * 64 + j] = acc;
    }
    if (blockIdx.x == 0 && tid < 64) {
        float acc = 0.0f;
        #pragma unroll 8
        for (int k = 0; k < 64; k++) acc = fmaf(__ldg(&embB[k]), Wsh[k * 64 + tid], acc);
        d_b0[tid] = acc;
    }
}

// ---------------- layer GEMM: X[nrows,K] @ W[K,64] (+bias) -> xp (fp16), + attention logits ----------------
template<int K, int NB, bool BNF, bool BIAS>
__global__ void gemm4_kernel(const float* __restrict__ X, const float* __restrict__ W,
                             const float* __restrict__ attS, const float* __restrict__ attD,
                             __half* __restrict__ out,
                             float* __restrict__ asOut, float* __restrict__ adOut,
                             const float* __restrict__ bias,
                             int nrows)
{
    constexpr int U = NB / 16;
    __shared__ float Wsh[K * 64];
    __shared__ float Xsh[NB * K];
    int tid = threadIdx.x;
    for (int i = tid; i < K * 64; i += 256) Wsh[i] = W[i];
    int nb = blockIdx.x * NB;
    for (int i = tid; i < NB * K; i += 256) {
        int r = i / K, k = i - r * K;
        int row = nb + r;
        float v = (row < nrows) ? __ldg(&X[row * K + k]) : 0.0f;
        if (BNF) v = elu(fmaf(v, d_bnscale[k], d_bnshift[k]));
        Xsh[i] = v;
    }
    __syncthreads();

    int lane = tid & 31;
    int cs = tid & 15, rs = tid >> 4;
    int j4 = cs * 4;
    float acc[U][4];
    #pragma unroll
    for (int u = 0; u < U; u++)
        #pragma unroll
        for (int c = 0; c < 4; c++) acc[u][c] = 0.0f;

    #pragma unroll 4
    for (int k = 0; k < K; k++) {
        float4 w = *reinterpret_cast<const float4*>(&Wsh[k * 64 + j4]);
        #pragma unroll
        for (int u = 0; u < U; u++) {
            float xv = Xsh[(rs + 16 * u) * K + k];
            acc[u][0] = fmaf(xv, w.x, acc[u][0]);
            acc[u][1] = fmaf(xv, w.y, acc[u][1]);
            acc[u][2] = fmaf(xv, w.z, acc[u][2]);
            acc[u][3] = fmaf(xv, w.w, acc[u][3]);
        }
    }

    float4 es = *reinterpret_cast<const float4*>(&attS[j4]);
    float4 ed = *reinterpret_cast<const float4*>(&attD[j4]);
    float4 bv = make_float4(0.f, 0.f, 0.f, 0.f);
    if (BIAS) bv = *reinterpret_cast<const float4*>(&bias[j4]);
    int head = cs >> 2;

    #pragma unroll
    for (int u = 0; u < U; u++) {
        int row = nb + rs + 16 * u;
        float4 v = make_float4(acc[u][0] + bv.x, acc[u][1] + bv.y,
                               acc[u][2] + bv.z, acc[u][3] + bv.w);
        if (row < nrows) {
            __half2 p0 = __float22half2_rn(make_float2(v.x, v.y));
            __half2 p1 = __float22half2_rn(make_float2(v.z, v.w));
            uint2 st;
            st.x = *reinterpret_cast<unsigned int*>(&p0);
            st.y = *reinterpret_cast<unsigned int*>(&p1);
            *reinterpret_cast<uint2*>(&out[row * 64 + j4]) = st;
        }
        float vs = v.x * es.x + v.y * es.y + v.z * es.z + v.w * es.w;
        float vd = v.x * ed.x + v.y * ed.y + v.z * ed.z + v.w * ed.w;
        vs += __shfl_xor_sync(0xffffffffu, vs, 1);
        vd += __shfl_xor_sync(0xffffffffu, vd, 1);
        vs += __shfl_xor_sync(0xffffffffu, vs, 2);
        vd += __shfl_xor_sync(0xffffffffu, vd, 2);
        if ((lane & 3) == 0 && row < nrows) {
            asOut[row * 4 + head] = vs;
            adOut[row * 4 + head] = vd;
        }
    }
}

// ---------------- attention gather: warp/node, single pass, fp16 xp, ELL rows ----------------
__device__ __forceinline__ void load_xp4(int base_idx, float& x0, float& x1, float& x2, float& x3) {
    uint2 raw = *reinterpret_cast<const uint2*>(&d_xp[base_idx]);
    __half2 h0 = *reinterpret_cast<__half2*>(&raw.x);
    __half2 h1 = *reinterpret_cast<__half2*>(&raw.y);
    float2 f0 = __half22float2(h0);
    float2 f1 = __half22float2(h1);
    x0 = f0.x; x1 = f0.y; x2 = f1.x; x3 = f1.y;
}

template<bool LAST>
__global__ void gather_kernel(const float* __restrict__ gb,
                              const float* __restrict__ gamma,
                              const float* __restrict__ beta)
{
    __shared__ float shsum[64], shsq[64];
    if (threadIdx.x < 64) { shsum[threadIdx.x] = 0.0f; shsq[threadIdx.x] = 0.0f; }
    // last layer: zero d_g for pool (blocks 0..63 cover 16384 floats)
    if (LAST && blockIdx.x < 64) d_g[blockIdx.x * 256 + threadIdx.x] = 0.0f;
    __syncthreads();

    int lane = threadIdx.x & 31;
    int half = lane >> 4;
    int l15  = lane & 15;
    int h    = l15 >> 2;
    int n = blockIdx.x * 8 + (threadIdx.x >> 5);
    {
        int cnt = d_cnt[n];
        if (LAST && lane == 0) d_cnt[n] = 0;   // ready for next call's ell_scatter
        int base = n * DEGCAP;
        float adh = __ldg(&d_ad[n * 4 + h]);

        float ax = 0.0f, ay = 0.0f, az = 0.0f, aw = 0.0f, ssum = 0.0f;
        if (half == 0) {
            // self loop: src = n
            float a = __ldg(&d_as[n * 4 + h]);
            float p = __expf(lrelu(a + adh));
            float x0, x1, x2, x3;
            load_xp4(n * 64 + 4 * l15, x0, x1, x2, x3);
            ssum = p;
            ax = x0 * p; ay = x1 * p; az = x2 * p; aw = x3 * p;
        }
        int i = half;
        // batched: 4 edges per half-warp iteration, all loads issued before use
        for (; i + 6 < cnt; i += 8) {
            int s0 = __ldg(&d_ell[base + i]);
            int s1 = __ldg(&d_ell[base + i + 2]);
            int s2 = __ldg(&d_ell[base + i + 4]);
            int s3 = __ldg(&d_ell[base + i + 6]);
            float a0 = __ldg(&d_as[s0 * 4 + h]);
            float a1 = __ldg(&d_as[s1 * 4 + h]);
            float a2 = __ldg(&d_as[s2 * 4 + h]);
            float a3 = __ldg(&d_as[s3 * 4 + h]);
            uint2 r0 = *reinterpret_cast<const uint2*>(&d_xp[s0 * 64 + 4 * l15]);
            uint2 r1 = *reinterpret_cast<const uint2*>(&d_xp[s1 * 64 + 4 * l15]);
            uint2 r2 = *reinterpret_cast<const uint2*>(&d_xp[s2 * 64 + 4 * l15]);
            uint2 r3 = *reinterpret_cast<const uint2*>(&d_xp[s3 * 64 + 4 * l15]);
            float p0 = __expf(lrelu(a0 + adh));
            float p1 = __expf(lrelu(a1 + adh));
            float p2 = __expf(lrelu(a2 + adh));
            float p3 = __expf(lrelu(a3 + adh));
            {
                float2 f0 = __half22float2(*reinterpret_cast<__half2*>(&r0.x));
                float2 f1 = __half22float2(*reinterpret_cast<__half2*>(&r0.y));
                ssum += p0;
                ax = fmaf(f0.x, p0, ax); ay = fmaf(f0.y, p0, ay);
                az = fmaf(f1.x, p0, az); aw = fmaf(f1.y, p0, aw);
            }
            {
                float2 f0 = __half22float2(*reinterpret_cast<__half2*>(&r1.x));
                float2 f1 = __half22float2(*reinterpret_cast<__half2*>(&r1.y));
                ssum += p1;
                ax = fmaf(f0.x, p1, ax); ay = fmaf(f0.y, p1, ay);
                az = fmaf(f1.x, p1, az); aw = fmaf(f1.y, p1, aw);
            }
            {
                float2 f0 = __half22float2(*reinterpret_cast<__half2*>(&r2.x));
                float2 f1 = __half22float2(*reinterpret_cast<__half2*>(&r2.y));
                ssum += p2;
                ax = fmaf(f0.x, p2, ax); ay = fmaf(f0.y, p2, ay);
                az = fmaf(f1.x, p2, az); aw = fmaf(f1.y, p2, aw);
            }
            {
                float2 f0 = __half22float2(*reinterpret_cast<__half2*>(&r3.x));
                float2 f1 = __half22float2(*reinterpret_cast<__half2*>(&r3.y));
                ssum += p3;
                ax = fmaf(f0.x, p3, ax); ay = fmaf(f0.y, p3, ay);
                az = fmaf(f1.x, p3, az); aw = fmaf(f1.y, p3, aw);
            }
        }
        // remainder (0..3 edges per half)
        for (; i < cnt; i += 2) {
            int s = __ldg(&d_ell[base + i]);
            float a = __ldg(&d_as[s * 4 + h]);
            float x0, x1, x2, x3;
            load_xp4(s * 64 + 4 * l15, x0, x1, x2, x3);
            float p = __expf(lrelu(a + adh));
            ssum += p;
            ax = fmaf(x0, p, ax);
            ay = fmaf(x1, p, ay);
            az = fmaf(x2, p, az);
            aw = fmaf(x3, p, aw);
        }
        // combine halves
        ssum += __shfl_xor_sync(0xffffffffu, ssum, 16);
        ax   += __shfl_xor_sync(0xffffffffu, ax, 16);
        ay   += __shfl_xor_sync(0xffffffffu, ay, 16);
        az   += __shfl_xor_sync(0xffffffffu, az, 16);
        aw   += __shfl_xor_sync(0xffffffffu, aw, 16);

        if (half == 0) {
            float inv = 1.0f / (ssum + 1e-16f);
            float4 gbv = *reinterpret_cast<const float4*>(&gb[4 * l15]);
            float v0 = ax * inv + gbv.x;
            float v1 = ay * inv + gbv.y;
            float v2 = az * inv + gbv.z;
            float v3 = aw * inv + gbv.w;
            *reinterpret_cast<float4*>(&d_h[n * 64 + 4 * l15]) = make_float4(v0, v1, v2, v3);
            int c = 4 * l15;
            atomicAdd(&shsum[c],     v0); atomicAdd(&shsq[c],     v0 * v0);
            atomicAdd(&shsum[c + 1], v1); atomicAdd(&shsq[c + 1], v1 * v1);
            atomicAdd(&shsum[c + 2], v2); atomicAdd(&shsq[c + 2], v2 * v2);
            atomicAdd(&shsum[c + 3], v3); atomicAdd(&shsq[c + 3], v3 * v3);
        }
    }
    __syncthreads();
    if (threadIdx.x < 64) {
        atomicAdd(&d_bn[threadIdx.x],      shsum[threadIdx.x]);
        atomicAdd(&d_bn[64 + threadIdx.x], shsq[threadIdx.x]);
    }

    // last-block: fold BN stats into scale/shift, reset d_bn + ticket
    __threadfence();
    __shared__ unsigned int isLast;
    if (threadIdx.x == 0)
        isLast = (atomicInc(&d_tick, 0xffffffffu) == gridDim.x - 1) ? 1u : 0u;
    __syncthreads();
    if (isLast) {
        int j = threadIdx.x;
        if (j < 64) {
            const float invN = 1.0f / (float)NN;
            float sum = atomicAdd(&d_bn[j], 0.0f);
            float sq  = atomicAdd(&d_bn[64 + j], 0.0f);
            float mu  = sum * invN;
            float var = sq * invN - mu * mu;
            float sc  = rsqrtf(var + 1e-5f) * __ldg(&gamma[j]);
            d_bnscale[j] = sc;
            d_bnshift[j] = __ldg(&beta[j]) - mu * sc;
            d_bn[j] = 0.0f; d_bn[64 + j] = 0.0f;
        }
        if (j == 64) d_tick = 0;
    }
}

// ---------------- pooling (applies last layer's BN+ELU) + MLP head ----------------
__global__ void pool_kernel(const int* __restrict__ batch) {
    int tid = threadIdx.x;
    int base = blockIdx.x * 128;
    int j4 = (tid & 15) * 4;
    int nlane = tid >> 4;
    float4 sc = *reinterpret_cast<const float4*>(&d_bnscale[j4]);
    float4 sh = *reinterpret_cast<const float4*>(&d_bnshift[j4]);
    float4 acc = make_float4(0.f, 0.f, 0.f, 0.f);
    int curb = -1;
    #pragma unroll
    for (int k = 0; k < 8; k++) {
        int n = base + nlane + 16 * k;
        if (n >= NN) break;
        int b = __ldg(&batch[n]);
        float4 hv = *reinterpret_cast<const float4*>(&d_h[n * 64 + j4]);
        float4 v;
        v.x = elu(fmaf(hv.x, sc.x, sh.x));
        v.y = elu(fmaf(hv.y, sc.y, sh.y));
        v.z = elu(fmaf(hv.z, sc.z, sh.z));
        v.w = elu(fmaf(hv.w, sc.w, sh.w));
        if (b != curb) {
            if (curb >= 0) {
                atomicAdd(&d_g[curb * 64 + j4],     acc.x);
                atomicAdd(&d_g[curb * 64 + j4 + 1], acc.y);
                atomicAdd(&d_g[curb * 64 + j4 + 2], acc.z);
                atomicAdd(&d_g[curb * 64 + j4 + 3], acc.w);
            }
            curb = b; acc = v;
        } else {
            acc.x += v.x; acc.y += v.y; acc.z += v.z; acc.w += v.w;
        }
    }
    if (curb >= 0) {
        atomicAdd(&d_g[curb * 64 + j4],     acc.x);
        atomicAdd(&d_g[curb * 64 + j4 + 1], acc.y);
        atomicAdd(&d_g[curb * 64 + j4 + 2], acc.z);
        atomicAdd(&d_g[curb * 64 + j4 + 3], acc.w);
    }
}

__global__ void head_kernel(const float* __restrict__ fc1W, const float* __restrict__ fc1b,
                            const float* __restrict__ fc2W, const float* __restrict__ fc2b,
                            float* __restrict__ out)
{
    __shared__ float gv[64];
    __shared__ float partial[2];
    int g = blockIdx.x, j = threadIdx.x;
    gv[j] = d_g[g * 64 + j];
    __syncthreads();
    float acc = __ldg(&fc1b[j]);
    #pragma unroll
    for (int k = 0; k < 64; k++) acc = fmaf(gv[k], __ldg(&fc1W[k * 64 + j]), acc);
    acc = fmaxf(acc, 0.0f) * __ldg(&fc2W[j]);
    #pragma unroll
    for (int off = 16; off; off >>= 1) acc += __shfl_xor_sync(0xffffffffu, acc, off);
    if ((j & 31) == 0) partial[j >> 5] = acc;
    __syncthreads();
    if (j == 0) out[g] = partial[0] + partial[1] + __ldg(&fc2b[0]);
}

// ---------------- launch ----------------
extern "C" void kernel_launch(void* const* d_in, const int* in_sizes, int n_in,
                              void* d_out, int out_size)
{
    const float* x     = (const float*)d_in[0];
    const float* embW  = (const float*)d_in[1];
    const float* embB  = (const float*)d_in[2];
    const float* gatW  = (const float*)d_in[3];
    const float* attS  = (const float*)d_in[4];
    const float* attD  = (const float*)d_in[5];
    const float* gatB  = (const float*)d_in[6];
    const float* bnG   = (const float*)d_in[7];
    const float* bnB   = (const float*)d_in[8];
    const float* fc1W  = (const float*)d_in[9];
    const float* fc1b  = (const float*)d_in[10];
    const float* fc2W  = (const float*)d_in[11];
    const float* fc2b  = (const float*)d_in[12];
    const int*   ei    = (const int*)d_in[13];
    const int*   batch = (const int*)d_in[14];
    float* out = (float*)d_out;

    void* p;
    cudaGetSymbolAddress(&p, d_xp); __half* xp  = (__half*)p;
    cudaGetSymbolAddress(&p, d_as); float*  pas = (float*)p;
    cudaGetSymbolAddress(&p, d_ad); float*  pad = (float*)p;
    cudaGetSymbolAddress(&p, d_w0); float*  w0  = (float*)p;
    cudaGetSymbolAddress(&p, d_b0); float*  b0  = (float*)p;
    cudaGetSymbolAddress(&p, d_h);  float*  h   = (float*)p;

    // side stream + fork/join events (created once, on the uncaptured correctness
    // call; graph topology is identical on every capture — work stays deterministic)
    static cudaStream_t s2 = nullptr;
    static cudaEvent_t evFork = nullptr, evJoin = nullptr;
    if (s2 == nullptr) {
        cudaStreamCreateWithFlags(&s2, cudaStreamNonBlocking);
        cudaEventCreateWithFlags(&evFork, cudaEventDisableTiming);
        cudaEventCreateWithFlags(&evJoin, cudaEventDisableTiming);
    }

    const int TB = 256;

    // fork: branch A (s2) builds ELL adjacency while branch B runs combine + layer-0 GEMM
    cudaEventRecord(evFork, 0);
    cudaStreamWaitEvent(s2, evFork, 0);

    // --- branch A: ELL adjacency (one kernel; d_cnt was reset by previous call) ---
    ell_scatter_kernel<<<(EE / 2 + TB - 1) / TB, TB, 0, s2>>>(ei);
    cudaEventRecord(evJoin, s2);

    // --- branch B: combined weights + layer-0 transform directly from x ---
    combine_kernel<<<8, 256>>>(embW, embB, gatW);
    gemm4_kernel<128, 32, false, true><<<(NN + 31) / 32, 256>>>(
        x, w0, attS, attD, xp, pas, pad, b0, NN);

    // join: gather needs ELL + xp/as/ad
    cudaStreamWaitEvent(0, evJoin, 0);

    gather_kernel<false><<<NN / 8, 256>>>(gatB, bnG, bnB);

    // layers 1..3 (prev layer's BN+ELU fused into GEMM X-load)
    for (int l = 1; l < NLAYERS; l++) {
        gemm4_kernel<64, 128, true, false><<<(NN + 127) / 128, 256>>>(
            h, gatW + l * 64 * 64, attS + l * 64, attD + l * 64,
            xp, pas, pad, nullptr, NN);
        if (l < NLAYERS - 1)
            gather_kernel<false><<<NN / 8, 256>>>(gatB + l * 64, bnG + l * 64, bnB + l * 64);
        else
            gather_kernel<true><<<NN / 8, 256>>>(gatB + l * 64, bnG + l * 64, bnB + l * 64);
    }

    // pool (applies layer-3 BN+ELU) + head
    pool_kernel<<<(NN + 127) / 128, 256>>>(batch);
    head_kernel<<<GG, 64>>>(fc1W, fc1b, fc2W, fc2b, out);
}

// round 15
// speedup vs baseline: 1.0454x; 1.0454x over previous
#include <cuda_runtime.h>
#include <cuda_fp16.h>
#include <math.h>

#define NN 50000
#define EE 800000
#define GG 256
#define NLAYERS 4
#define SCAN_BLK ((NN + 1023) / 1024)   // 49

// ---------------- static device scratch ----------------
__device__ __align__(16) float  d_h [NN * 64];
__device__ __align__(16) __half d_xp[NN * 64];   // fp16 messages
__device__ __align__(16) float  d_as[NN * 4];
__device__ __align__(16) float  d_ad[NN * 4];
__device__ int   d_cnt[NN];          // kept zeroed between calls
__device__ int   d_rowptr[NN + 1];
__device__ int   d_cursor[NN];
__device__ int   d_bsum[SCAN_BLK];
__device__ int   d_csrc[EE];         // real edges only; self-loops handled inline
__device__ float d_bn[128];          // kept zeroed between calls
__device__ float d_bnscale[64];
__device__ float d_bnshift[64];
__device__ float d_g [GG * 64];
__device__ unsigned int d_tick;      // last-block ticket (kept zeroed)

__device__ __forceinline__ float lrelu(float x) { return x > 0.0f ? x : 0.2f * x; }
__device__ __forceinline__ float elu(float x)   { return x > 0.0f ? x : expm1f(x); }

// ---------------- CSR build ----------------
__global__ void hist_kernel(const int* __restrict__ ei) {
    int i0 = (blockIdx.x * blockDim.x + threadIdx.x) * 2;
    if (i0 < EE) {
        int2 dd = *reinterpret_cast<const int2*>(&ei[EE + i0]);   // EE even, i0 even -> aligned
        atomicAdd(&d_cnt[dd.x], 1);
        atomicAdd(&d_cnt[dd.y], 1);
    }
}

// block-local exclusive scan (1024/block)
__global__ void scanA_kernel() {
    __shared__ int wsum[32];
    int i = blockIdx.x * 1024 + threadIdx.x;
    int lane = threadIdx.x & 31, warp = threadIdx.x >> 5;
    int v = (i < NN) ? d_cnt[i] : 0;
    int orig = v;
    #pragma unroll
    for (int off = 1; off < 32; off <<= 1) {
        int t = __shfl_up_sync(0xffffffffu, v, off);
        if (lane >= off) v += t;
    }
    if (lane == 31) wsum[warp] = v;
    __syncthreads();
    if (threadIdx.x < 32) {
        int w = wsum[threadIdx.x];
        #pragma unroll
        for (int off = 1; off < 32; off <<= 1) {
            int t = __shfl_up_sync(0xffffffffu, w, off);
            if (lane >= off) w += t;
        }
        wsum[threadIdx.x] = w;
    }
    __syncthreads();
    int prefix = warp ? wsum[warp - 1] : 0;
    int incl = v + prefix;
    if (i < NN) d_rowptr[i] = incl - orig;
    if (threadIdx.x == 1023) d_bsum[blockIdx.x] = incl;
}

// fused: block-prefix (inline), cursor copy, cnt reset, zero d_g, rowptr[NN]
__global__ void scanC_kernel() {
    int i = blockIdx.x * blockDim.x + threadIdx.x;
    if (i < NN) {
        int blk = i >> 10;
        int prefix = 0;
        for (int b = 0; b < blk; b++) prefix += __ldg(&d_bsum[b]);
        int r = d_rowptr[i] + prefix;
        d_rowptr[i] = r;
        d_cursor[i] = r;
        d_cnt[i] = 0;
    }
    if (i == 0) d_rowptr[NN] = EE;
    if (i < GG * 64) d_g[i] = 0.0f;
}

__global__ void scatter_kernel(const int* __restrict__ ei) {
    int i0 = (blockIdx.x * blockDim.x + threadIdx.x) * 2;
    if (i0 < EE) {
        int2 dd = *reinterpret_cast<const int2*>(&ei[EE + i0]);
        int2 ss = *reinterpret_cast<const int2*>(&ei[i0]);
        int p0 = atomicAdd(&d_cursor[dd.x], 1);
        int p1 = atomicAdd(&d_cursor[dd.y], 1);
        d_csrc[p0] = ss.x;
        d_csrc[p1] = ss.y;
    }
}

// ---------------- embed GEMM: X[nrows,128] @ W[128,64] + bias ----------------
template<int K, int NB>
__global__ void gemm2_kernel(const float* __restrict__ X, const float* __restrict__ W,
                             const float* __restrict__ bias, float* __restrict__ out,
                             int nrows)
{
    constexpr int U = NB / 8;
    __shared__ float Wsh[K * 64];
    __shared__ float Xsh[NB * K];
    int tid = threadIdx.x;
    for (int i = tid; i < K * 64; i += 256) Wsh[i] = W[i];
    int nb = blockIdx.x * NB;
    for (int i = tid; i < NB * K; i += 256) {
        int r = i / K, k = i - r * K;
        int row = nb + r;
        Xsh[i] = (row < nrows) ? __ldg(&X[row * K + k]) : 0.0f;
    }
    __syncthreads();

    int lane = tid & 31;
    int jp   = lane * 2;
    int r0   = tid >> 5;
    float acc0[U], acc1[U];
    #pragma unroll
    for (int u = 0; u < U; u++) { acc0[u] = 0.0f; acc1[u] = 0.0f; }

    #pragma unroll 4
    for (int k = 0; k < K; k++) {
        float2 w = *reinterpret_cast<const float2*>(&Wsh[k * 64 + jp]);
        #pragma unroll
        for (int u = 0; u < U; u++) {
            float xv = Xsh[(r0 + 8 * u) * K + k];
            acc0[u] = fmaf(xv, w.x, acc0[u]);
            acc1[u] = fmaf(xv, w.y, acc1[u]);
        }
    }
    float b0 = __ldg(&bias[jp]), b1 = __ldg(&bias[jp + 1]);
    #pragma unroll
    for (int u = 0; u < U; u++) {
        int row = nb + r0 + 8 * u;
        if (row < nrows)
            *reinterpret_cast<float2*>(&out[row * 64 + jp]) = make_float2(acc0[u] + b0, acc1[u] + b1);
    }
}

// ---------------- layer GEMM: h[N,64] @ W[64,64] -> xp (fp16), + attention logits ----------------
template<int K, int NB, bool BNF>
__global__ void gemm4_kernel(const float* __restrict__ X, const float* __restrict__ W,
                             const float* __restrict__ attS, const float* __restrict__ attD,
                             __half* __restrict__ out,
                             float* __restrict__ asOut, float* __restrict__ adOut,
                             int nrows)
{
    constexpr int U = NB / 16;
    __shared__ float Wsh[K * 64];
    __shared__ float Xsh[NB * K];
    int tid = threadIdx.x;
    for (int i = tid; i < K * 64; i += 256) Wsh[i] = W[i];
    int nb = blockIdx.x * NB;
    for (int i = tid; i < NB * K; i += 256) {
        int r = i / K, k = i - r * K;
        int row = nb + r;
        float v = (row < nrows) ? __ldg(&X[row * K + k]) : 0.0f;
        if (BNF) v = elu(fmaf(v, d_bnscale[k], d_bnshift[k]));
        Xsh[i] = v;
    }
    __syncthreads();

    int lane = tid & 31;
    int cs = tid & 15, rs = tid >> 4;
    int j4 = cs * 4;
    float acc[U][4];
    #pragma unroll
    for (int u = 0; u < U; u++)
        #pragma unroll
        for (int c = 0; c < 4; c++) acc[u][c] = 0.0f;

    #pragma unroll 4
    for (int k = 0; k < K; k++) {
        float4 w = *reinterpret_cast<const float4*>(&Wsh[k * 64 + j4]);
        #pragma unroll
        for (int u = 0; u < U; u++) {
            float xv = Xsh[(rs + 16 * u) * K + k];
            acc[u][0] = fmaf(xv, w.x, acc[u][0]);
            acc[u][1] = fmaf(xv, w.y, acc[u][1]);
            acc[u][2] = fmaf(xv, w.z, acc[u][2]);
            acc[u][3] = fmaf(xv, w.w, acc[u][3]);
        }
    }

    float4 es = *reinterpret_cast<const float4*>(&attS[j4]);
    float4 ed = *reinterpret_cast<const float4*>(&attD[j4]);
    int head = cs >> 2;

    #pragma unroll
    for (int u = 0; u < U; u++) {
        int row = nb + rs + 16 * u;
        float4 v = make_float4(acc[u][0], acc[u][1], acc[u][2], acc[u][3]);
        if (row < nrows) {
            __half2 p0 = __float22half2_rn(make_float2(v.x, v.y));
            __half2 p1 = __float22half2_rn(make_float2(v.z, v.w));
            uint2 st;
            st.x = *reinterpret_cast<unsigned int*>(&p0);
            st.y = *reinterpret_cast<unsigned int*>(&p1);
            *reinterpret_cast<uint2*>(&out[row * 64 + j4]) = st;
        }
        float vs = v.x * es.x + v.y * es.y + v.z * es.z + v.w * es.w;
        float vd = v.x * ed.x + v.y * ed.y + v.z * ed.z + v.w * ed.w;
        vs += __shfl_xor_sync(0xffffffffu, vs, 1);
        vd += __shfl_xor_sync(0xffffffffu, vd, 1);
        vs += __shfl_xor_sync(0xffffffffu, vs, 2);
        vd += __shfl_xor_sync(0xffffffffu, vd, 2);
        if ((lane & 3) == 0 && row < nrows) {
            asOut[row * 4 + head] = vs;
            adOut[row * 4 + head] = vd;
        }
    }
}

// ---------------- attention gather: warp/node, QUARTER-split, fp16 xp, bnfin fused ----------------
// quarter q = lane>>3 owns edges i = beg+q (mod 4); lane owns 8 channels j8 = 8*(lane&7);
// head h = (lane&7)>>1. 25% fewer warp instructions per edge than the half-split.
__global__ void gather_kernel(const float* __restrict__ gb,
                              const float* __restrict__ gamma,
                              const float* __restrict__ beta)
{
    __shared__ float shsum[64], shsq[64];
    if (threadIdx.x < 64) { shsum[threadIdx.x] = 0.0f; shsq[threadIdx.x] = 0.0f; }
    __syncthreads();

    int lane = threadIdx.x & 31;
    int q  = lane >> 3;     // quarter 0..3
    int l8 = lane & 7;      // lane within quarter
    int h  = l8 >> 1;       // head 0..3
    int j8 = l8 * 8;        // 8 channels per lane
    int n = blockIdx.x * 8 + (threadIdx.x >> 5);
    {
        int beg = d_rowptr[n], end = d_rowptr[n + 1];
        float adh = __ldg(&d_ad[n * 4 + h]);

        float acc0 = 0.f, acc1 = 0.f, acc2 = 0.f, acc3 = 0.f;
        float acc4 = 0.f, acc5 = 0.f, acc6 = 0.f, acc7 = 0.f;
        float ssum = 0.0f;
        if (q == 0) {
            // self loop: src = n
            float a = __ldg(&d_as[n * 4 + h]);
            float p = __expf(lrelu(a + adh));
            uint4 r = *reinterpret_cast<const uint4*>(&d_xp[n * 64 + j8]);
            float2 f0 = __half22float2(*reinterpret_cast<__half2*>(&r.x));
            float2 f1 = __half22float2(*reinterpret_cast<__half2*>(&r.y));
            float2 f2 = __half22float2(*reinterpret_cast<__half2*>(&r.z));
            float2 f3 = __half22float2(*reinterpret_cast<__half2*>(&r.w));
            ssum = p;
            acc0 = f0.x * p; acc1 = f0.y * p; acc2 = f1.x * p; acc3 = f1.y * p;
            acc4 = f2.x * p; acc5 = f2.y * p; acc6 = f3.x * p; acc7 = f3.y * p;
        }
        #pragma unroll 2
        for (int i = beg + q; i < end; i += 4) {
            int s = __ldg(&d_csrc[i]);
            float a = __ldg(&d_as[s * 4 + h]);
            uint4 r = *reinterpret_cast<const uint4*>(&d_xp[s * 64 + j8]);
            float p = __expf(lrelu(a + adh));
            ssum += p;
            float2 f0 = __half22float2(*reinterpret_cast<__half2*>(&r.x));
            float2 f1 = __half22float2(*reinterpret_cast<__half2*>(&r.y));
            float2 f2 = __half22float2(*reinterpret_cast<__half2*>(&r.z));
            float2 f3 = __half22float2(*reinterpret_cast<__half2*>(&r.w));
            acc0 = fmaf(f0.x, p, acc0); acc1 = fmaf(f0.y, p, acc1);
            acc2 = fmaf(f1.x, p, acc2); acc3 = fmaf(f1.y, p, acc3);
            acc4 = fmaf(f2.x, p, acc4); acc5 = fmaf(f2.y, p, acc5);
            acc6 = fmaf(f3.x, p, acc6); acc7 = fmaf(f3.y, p, acc7);
        }
        // combine quarters (xor 8, then 16)
        ssum += __shfl_xor_sync(0xffffffffu, ssum, 8);
        acc0 += __shfl_xor_sync(0xffffffffu, acc0, 8);
        acc1 += __shfl_xor_sync(0xffffffffu, acc1, 8);
        acc2 += __shfl_xor_sync(0xffffffffu, acc2, 8);
        acc3 += __shfl_xor_sync(0xffffffffu, acc3, 8);
        acc4 += __shfl_xor_sync(0xffffffffu, acc4, 8);
        acc5 += __shfl_xor_sync(0xffffffffu, acc5, 8);
        acc6 += __shfl_xor_sync(0xffffffffu, acc6, 8);
        acc7 += __shfl_xor_sync(0xffffffffu, acc7, 8);
        ssum += __shfl_xor_sync(0xffffffffu, ssum, 16);
        acc0 += __shfl_xor_sync(0xffffffffu, acc0, 16);
        acc1 += __shfl_xor_sync(0xffffffffu, acc1, 16);
        acc2 += __shfl_xor_sync(0xffffffffu, acc2, 16);
        acc3 += __shfl_xor_sync(0xffffffffu, acc3, 16);
        acc4 += __shfl_xor_sync(0xffffffffu, acc4, 16);
        acc5 += __shfl_xor_sync(0xffffffffu, acc5, 16);
        acc6 += __shfl_xor_sync(0xffffffffu, acc6, 16);
        acc7 += __shfl_xor_sync(0xffffffffu, acc7, 16);

        if (q == 0) {
            float inv = 1.0f / (ssum + 1e-16f);
            float4 gb0 = *reinterpret_cast<const float4*>(&gb[j8]);
            float4 gb1 = *reinterpret_cast<const float4*>(&gb[j8 + 4]);
            float v0 = acc0 * inv + gb0.x;
            float v1 = acc1 * inv + gb0.y;
            float v2 = acc2 * inv + gb0.z;
            float v3 = acc3 * inv + gb0.w;
            float v4 = acc4 * inv + gb1.x;
            float v5 = acc5 * inv + gb1.y;
            float v6 = acc6 * inv + gb1.z;
            float v7 = acc7 * inv + gb1.w;
            *reinterpret_cast<float4*>(&d_h[n * 64 + j8])     = make_float4(v0, v1, v2, v3);
            *reinterpret_cast<float4*>(&d_h[n * 64 + j8 + 4]) = make_float4(v4, v5, v6, v7);
            atomicAdd(&shsum[j8],     v0); atomicAdd(&shsq[j8],     v0 * v0);
            atomicAdd(&shsum[j8 + 1], v1); atomicAdd(&shsq[j8 + 1], v1 * v1);
            atomicAdd(&shsum[j8 + 2], v2); atomicAdd(&shsq[j8 + 2], v2 * v2);
            atomicAdd(&shsum[j8 + 3], v3); atomicAdd(&shsq[j8 + 3], v3 * v3);
            atomicAdd(&shsum[j8 + 4], v4); atomicAdd(&shsq[j8 + 4], v4 * v4);
            atomicAdd(&shsum[j8 + 5], v5); atomicAdd(&shsq[j8 + 5], v5 * v5);
            atomicAdd(&shsum[j8 + 6], v6); atomicAdd(&shsq[j8 + 6], v6 * v6);
            atomicAdd(&shsum[j8 + 7], v7); atomicAdd(&shsq[j8 + 7], v7 * v7);
        }
    }
    __syncthreads();
    if (threadIdx.x < 64) {
        atomicAdd(&d_bn[threadIdx.x],      shsum[threadIdx.x]);
        atomicAdd(&d_bn[64 + threadIdx.x], shsq[threadIdx.x]);
    }

    // last-block: fold BN stats into scale/shift, reset d_bn + ticket
    __threadfence();
    __shared__ unsigned int isLast;
    if (threadIdx.x == 0)
        isLast = (atomicInc(&d_tick, 0xffffffffu) == gridDim.x - 1) ? 1u : 0u;
    __syncthreads();
    if (isLast) {
        int j = threadIdx.x;
        if (j < 64) {
            const float invN = 1.0f / (float)NN;
            float sum = atomicAdd(&d_bn[j], 0.0f);
            float sq  = atomicAdd(&d_bn[64 + j], 0.0f);
            float mu  = sum * invN;
            float var = sq * invN - mu * mu;
            float sc  = rsqrtf(var + 1e-5f) * __ldg(&gamma[j]);
            d_bnscale[j] = sc;
            d_bnshift[j] = __ldg(&beta[j]) - mu * sc;
            d_bn[j] = 0.0f; d_bn[64 + j] = 0.0f;
        }
        if (j == 64) d_tick = 0;
    }
}

// ---------------- pooling (applies last layer's BN+ELU) + MLP head ----------------
__global__ void pool_kernel(const int* __restrict__ batch) {
    int tid = threadIdx.x;
    int base = blockIdx.x * 128;
    int j4 = (tid & 15) * 4;
    int nlane = tid >> 4;
    float4 sc = *reinterpret_cast<const float4*>(&d_bnscale[j4]);
    float4 sh = *reinterpret_cast<const float4*>(&d_bnshift[j4]);
    float4 acc = make_float4(0.f, 0.f, 0.f, 0.f);
    int curb = -1;
    #pragma unroll
    for (int k = 0; k < 8; k++) {
        int n = base + nlane + 16 * k;
        if (n >= NN) break;
        int b = __ldg(&batch[n]);
        float4 hv = *reinterpret_cast<const float4*>(&d_h[n * 64 + j4]);
        float4 v;
        v.x = elu(fmaf(hv.x, sc.x, sh.x));
        v.y = elu(fmaf(hv.y, sc.y, sh.y));
        v.z = elu(fmaf(hv.z, sc.z, sh.z));
        v.w = elu(fmaf(hv.w, sc.w, sh.w));
        if (b != curb) {
            if (curb >= 0) {
                atomicAdd(&d_g[curb * 64 + j4],     acc.x);
                atomicAdd(&d_g[curb * 64 + j4 + 1], acc.y);
                atomicAdd(&d_g[curb * 64 + j4 + 2], acc.z);
                atomicAdd(&d_g[curb * 64 + j4 + 3], acc.w);
            }
            curb = b; acc = v;
        } else {
            acc.x += v.x; acc.y += v.y; acc.z += v.z; acc.w += v.w;
        }
    }
    if (curb >= 0) {
        atomicAdd(&d_g[curb * 64 + j4],     acc.x);
        atomicAdd(&d_g[curb * 64 + j4 + 1], acc.y);
        atomicAdd(&d_g[curb * 64 + j4 + 2], acc.z);
        atomicAdd(&d_g[curb * 64 + j4 + 3], acc.w);
    }
}

__global__ void head_kernel(const float* __restrict__ fc1W, const float* __restrict__ fc1b,
                            const float* __restrict__ fc2W, const float* __restrict__ fc2b,
                            float* __restrict__ out)
{
    __shared__ float gv[64];
    __shared__ float partial[2];
    int g = blockIdx.x, j = threadIdx.x;
    gv[j] = d_g[g * 64 + j];
    __syncthreads();
    float acc = __ldg(&fc1b[j]);
    #pragma unroll
    for (int k = 0; k < 64; k++) acc = fmaf(gv[k], __ldg(&fc1W[k * 64 + j]), acc);
    acc = fmaxf(acc, 0.0f) * __ldg(&fc2W[j]);
    #pragma unroll
    for (int off = 16; off; off >>= 1) acc += __shfl_xor_sync(0xffffffffu, acc, off);
    if ((j & 31) == 0) partial[j >> 5] = acc;
    __syncthreads();
    if (j == 0) out[g] = partial[0] + partial[1] + __ldg(&fc2b[0]);
}

// ---------------- launch ----------------
extern "C" void kernel_launch(void* const* d_in, const int* in_sizes, int n_in,
                              void* d_out, int out_size)
{
    const float* x     = (const float*)d_in[0];
    const float* embW  = (const float*)d_in[1];
    const float* embB  = (const float*)d_in[2];
    const float* gatW  = (const float*)d_in[3];
    const float* attS  = (const float*)d_in[4];
    const float* attD  = (const float*)d_in[5];
    const float* gatB  = (const float*)d_in[6];
    const float* bnG   = (const float*)d_in[7];
    const float* bnB   = (const float*)d_in[8];
    const float* fc1W  = (const float*)d_in[9];
    const float* fc1b  = (const float*)d_in[10];
    const float* fc2W  = (const float*)d_in[11];
    const float* fc2b  = (const float*)d_in[12];
    const int*   ei    = (const int*)d_in[13];
    const int*   batch = (const int*)d_in[14];
    float* out = (float*)d_out;

    void* p;
    cudaGetSymbolAddress(&p, d_h);  float*  h   = (float*)p;
    cudaGetSymbolAddress(&p, d_xp); __half* xp  = (__half*)p;
    cudaGetSymbolAddress(&p, d_as); float*  pas = (float*)p;
    cudaGetSymbolAddress(&p, d_ad); float*  pad = (float*)p;

    // side stream + fork/join events (created once, on the uncaptured correctness
    // call; graph topology is identical on every capture — work stays deterministic)
    static cudaStream_t s2 = nullptr;
    static cudaEvent_t evFork = nullptr, evJoin = nullptr;
    if (s2 == nullptr) {
        cudaStreamCreateWithFlags(&s2, cudaStreamNonBlocking);
        cudaEventCreateWithFlags(&evFork, cudaEventDisableTiming);
        cudaEventCreateWithFlags(&evJoin, cudaEventDisableTiming);
    }

    const int TB = 256;

    // fork: branch A (s2) builds CSR while branch B (legacy) runs the GEMMs
    cudaEventRecord(evFork, 0);
    cudaStreamWaitEvent(s2, evFork, 0);

    // --- branch A: CSR by dst (real edges only) ---
    hist_kernel<<<(EE / 2 + TB - 1) / TB, TB, 0, s2>>>(ei);
    scanA_kernel<<<SCAN_BLK, 1024, 0, s2>>>();
    scanC_kernel<<<(NN + TB - 1) / TB, TB, 0, s2>>>();
    scatter_kernel<<<(EE / 2 + TB - 1) / TB, TB, 0, s2>>>(ei);
    cudaEventRecord(evJoin, s2);

    // --- branch B: node embedding + layer-0 transform ---
    gemm2_kernel<128, 32><<<(NN + 31) / 32, 256>>>(x, embW, embB, h, NN);
    gemm4_kernel<64, 128, false><<<(NN + 127) / 128, 256>>>(
        h, gatW, attS, attD, xp, pas, pad, NN);

    // join: gather needs CSR + xp/as/ad
    cudaStreamWaitEvent(0, evJoin, 0);

    gather_kernel<<<NN / 8, 256>>>(gatB, bnG, bnB);

    // layers 1..3 (prev layer's BN+ELU fused into GEMM X-load)
    for (int l = 1; l < NLAYERS; l++) {
        gemm4_kernel<64, 128, true><<<(NN + 127) / 128, 256>>>(
            h, gatW + l * 64 * 64, attS + l * 64, attD + l * 64,
            xp, pas, pad, NN);
        gather_kernel<<<NN / 8, 256>>>(gatB + l * 64, bnG + l * 64, bnB + l * 64);
    }

    // pool (applies layer-3 BN+ELU) + head
    pool_kernel<<<(NN + 127) / 128, 256>>>(batch);
    head_kernel<<<GG, 64>>>(fc1W, fc1b, fc2W, fc2b, out);
}

// round 16
// speedup vs baseline: 1.1958x; 1.1438x over previous
#include <cuda_runtime.h>
#include <cuda_fp16.h>
#include <math.h>

#define NN 50000
#define EE 800000
#define GG 256
#define NLAYERS 4
#define SCAN_BLK ((NN + 1023) / 1024)   // 49

// ---------------- static device scratch ----------------
__device__ __align__(16) float  d_h [NN * 64];
__device__ __align__(16) __half d_xp[NN * 64];   // fp16 messages
__device__ __align__(16) float  d_as[NN * 4];
__device__ __align__(16) float  d_ad[NN * 4];
__device__ int   d_cnt[NN];          // kept zeroed between calls
__device__ int   d_rowptr[NN + 1];
__device__ int   d_cursor[NN];
__device__ int   d_bsum[SCAN_BLK];
__device__ int   d_csrc[EE];         // real edges only; self-loops handled inline
__device__ float d_bn[128];          // kept zeroed between calls
__device__ __align__(16) float d_bnscale[64];
__device__ __align__(16) float d_bnshift[64];
__device__ float d_g [GG * 64];
__device__ unsigned int d_tick;      // last-block ticket (kept zeroed)

__device__ __forceinline__ float lrelu(float x) { return x > 0.0f ? x : 0.2f * x; }
__device__ __forceinline__ float elu(float x)   { return x > 0.0f ? x : expm1f(x); }

// ---------------- CSR build ----------------
__global__ void hist_kernel(const int* __restrict__ ei) {
    int i0 = (blockIdx.x * blockDim.x + threadIdx.x) * 2;
    if (i0 < EE) {
        int2 dd = *reinterpret_cast<const int2*>(&ei[EE + i0]);   // EE even, i0 even -> aligned
        atomicAdd(&d_cnt[dd.x], 1);
        atomicAdd(&d_cnt[dd.y], 1);
    }
}

// block-local exclusive scan (1024/block)
__global__ void scanA_kernel() {
    __shared__ int wsum[32];
    int i = blockIdx.x * 1024 + threadIdx.x;
    int lane = threadIdx.x & 31, warp = threadIdx.x >> 5;
    int v = (i < NN) ? d_cnt[i] : 0;
    int orig = v;
    #pragma unroll
    for (int off = 1; off < 32; off <<= 1) {
        int t = __shfl_up_sync(0xffffffffu, v, off);
        if (lane >= off) v += t;
    }
    if (lane == 31) wsum[warp] = v;
    __syncthreads();
    if (threadIdx.x < 32) {
        int w = wsum[threadIdx.x];
        #pragma unroll
        for (int off = 1; off < 32; off <<= 1) {
            int t = __shfl_up_sync(0xffffffffu, w, off);
            if (lane >= off) w += t;
        }
        wsum[threadIdx.x] = w;
    }
    __syncthreads();
    int prefix = warp ? wsum[warp - 1] : 0;
    int incl = v + prefix;
    if (i < NN) d_rowptr[i] = incl - orig;
    if (threadIdx.x == 1023) d_bsum[blockIdx.x] = incl;
}

// fused: block-prefix (inline), cursor copy, cnt reset, zero d_g, rowptr[NN]
__global__ void scanC_kernel() {
    int i = blockIdx.x * blockDim.x + threadIdx.x;
    if (i < NN) {
        int blk = i >> 10;
        int prefix = 0;
        for (int b = 0; b < blk; b++) prefix += __ldg(&d_bsum[b]);
        int r = d_rowptr[i] + prefix;
        d_rowptr[i] = r;
        d_cursor[i] = r;
        d_cnt[i] = 0;
    }
    if (i == 0) d_rowptr[NN] = EE;
    if (i < GG * 64) d_g[i] = 0.0f;
}

__global__ void scatter_kernel(const int* __restrict__ ei) {
    int i0 = (blockIdx.x * blockDim.x + threadIdx.x) * 2;
    if (i0 < EE) {
        int2 dd = *reinterpret_cast<const int2*>(&ei[EE + i0]);
        int2 ss = *reinterpret_cast<const int2*>(&ei[i0]);
        int p0 = atomicAdd(&d_cursor[dd.x], 1);
        int p1 = atomicAdd(&d_cursor[dd.y], 1);
        d_csrc[p0] = ss.x;
        d_csrc[p1] = ss.y;
    }
}

// ---------------- embed GEMM: X[nrows,128] @ W[128,64] + bias ----------------
template<int K, int NB>
__global__ void gemm2_kernel(const float* __restrict__ X, const float* __restrict__ W,
                             const float* __restrict__ bias, float* __restrict__ out,
                             int nrows)
{
    constexpr int U = NB / 8;
    constexpr int KQ = K / 4;
    __shared__ float Wsh[K * 64];
    __shared__ float Xsh[NB * K];
    int tid = threadIdx.x;
    for (int i = tid; i < K * 16; i += 256)
        reinterpret_cast<float4*>(Wsh)[i] = __ldg(&reinterpret_cast<const float4*>(W)[i]);
    int nb = blockIdx.x * NB;
    for (int i = tid; i < NB * KQ; i += 256) {
        int r = i / KQ, kq = i - r * KQ;
        int row = nb + r;
        float4 v = make_float4(0.f, 0.f, 0.f, 0.f);
        if (row < nrows) v = __ldg(&reinterpret_cast<const float4*>(X)[row * KQ + kq]);
        reinterpret_cast<float4*>(Xsh)[i] = v;
    }
    __syncthreads();

    int lane = tid & 31;
    int jp   = lane * 2;
    int r0   = tid >> 5;
    float acc0[U], acc1[U];
    #pragma unroll
    for (int u = 0; u < U; u++) { acc0[u] = 0.0f; acc1[u] = 0.0f; }

    #pragma unroll 4
    for (int k = 0; k < K; k++) {
        float2 w = *reinterpret_cast<const float2*>(&Wsh[k * 64 + jp]);
        #pragma unroll
        for (int u = 0; u < U; u++) {
            float xv = Xsh[(r0 + 8 * u) * K + k];
            acc0[u] = fmaf(xv, w.x, acc0[u]);
            acc1[u] = fmaf(xv, w.y, acc1[u]);
        }
    }
    float b0 = __ldg(&bias[jp]), b1 = __ldg(&bias[jp + 1]);
    #pragma unroll
    for (int u = 0; u < U; u++) {
        int row = nb + r0 + 8 * u;
        if (row < nrows)
            *reinterpret_cast<float2*>(&out[row * 64 + jp]) = make_float2(acc0[u] + b0, acc1[u] + b1);
    }
}

// ---------------- layer GEMM: h[N,64] @ W[64,64] -> xp (fp16), + attention logits ----------------
template<int K, int NB, bool BNF>
__global__ void gemm4_kernel(const float* __restrict__ X, const float* __restrict__ W,
                             const float* __restrict__ attS, const float* __restrict__ attD,
                             __half* __restrict__ out,
                             float* __restrict__ asOut, float* __restrict__ adOut,
                             int nrows)
{
    constexpr int U = NB / 16;
    constexpr int KQ = K / 4;
    __shared__ float Wsh[K * 64];
    __shared__ float Xsh[NB * K];
    int tid = threadIdx.x;
    for (int i = tid; i < K * 16; i += 256)
        reinterpret_cast<float4*>(Wsh)[i] = __ldg(&reinterpret_cast<const float4*>(W)[i]);
    int nb = blockIdx.x * NB;
    for (int i = tid; i < NB * KQ; i += 256) {
        int r = i / KQ, kq = i - r * KQ;
        int row = nb + r;
        float4 v = make_float4(0.f, 0.f, 0.f, 0.f);
        if (row < nrows) v = __ldg(&reinterpret_cast<const float4*>(X)[row * KQ + kq]);
        if (BNF) {
            float4 sc = *reinterpret_cast<const float4*>(&d_bnscale[kq * 4]);  // K==64 when BNF
            float4 sh = *reinterpret_cast<const float4*>(&d_bnshift[kq * 4]);
            v.x = elu(fmaf(v.x, sc.x, sh.x));
            v.y = elu(fmaf(v.y, sc.y, sh.y));
            v.z = elu(fmaf(v.z, sc.z, sh.z));
            v.w = elu(fmaf(v.w, sc.w, sh.w));
        }
        reinterpret_cast<float4*>(Xsh)[i] = v;
    }
    __syncthreads();

    int lane = tid & 31;
    int cs = tid & 15, rs = tid >> 4;
    int j4 = cs * 4;
    float acc[U][4];
    #pragma unroll
    for (int u = 0; u < U; u++)
        #pragma unroll
        for (int c = 0; c < 4; c++) acc[u][c] = 0.0f;

    #pragma unroll 4
    for (int k = 0; k < K; k++) {
        float4 w = *reinterpret_cast<const float4*>(&Wsh[k * 64 + j4]);
        #pragma unroll
        for (int u = 0; u < U; u++) {
            float xv = Xsh[(rs + 16 * u) * K + k];
            acc[u][0] = fmaf(xv, w.x, acc[u][0]);
            acc[u][1] = fmaf(xv, w.y, acc[u][1]);
            acc[u][2] = fmaf(xv, w.z, acc[u][2]);
            acc[u][3] = fmaf(xv, w.w, acc[u][3]);
        }
    }

    float4 es = *reinterpret_cast<const float4*>(&attS[j4]);
    float4 ed = *reinterpret_cast<const float4*>(&attD[j4]);
    int head = cs >> 2;

    #pragma unroll
    for (int u = 0; u < U; u++) {
        int row = nb + rs + 16 * u;
        float4 v = make_float4(acc[u][0], acc[u][1], acc[u][2], acc[u][3]);
        if (row < nrows) {
            __half2 p0 = __float22half2_rn(make_float2(v.x, v.y));
            __half2 p1 = __float22half2_rn(make_float2(v.z, v.w));
            uint2 st;
            st.x = *reinterpret_cast<unsigned int*>(&p0);
            st.y = *reinterpret_cast<unsigned int*>(&p1);
            *reinterpret_cast<uint2*>(&out[row * 64 + j4]) = st;
        }
        float vs = v.x * es.x + v.y * es.y + v.z * es.z + v.w * es.w;
        float vd = v.x * ed.x + v.y * ed.y + v.z * ed.z + v.w * ed.w;
        vs += __shfl_xor_sync(0xffffffffu, vs, 1);
        vd += __shfl_xor_sync(0xffffffffu, vd, 1);
        vs += __shfl_xor_sync(0xffffffffu, vs, 2);
        vd += __shfl_xor_sync(0xffffffffu, vd, 2);
        if ((lane & 3) == 0 && row < nrows) {
            asOut[row * 4 + head] = vs;
            adOut[row * 4 + head] = vd;
        }
    }
}

// ---------------- attention gather: warp/node, single pass, fp16 xp, 8 edges in flight ----------------
__device__ __forceinline__ void load_xp4(int base_idx, float& x0, float& x1, float& x2, float& x3) {
    uint2 raw = *reinterpret_cast<const uint2*>(&d_xp[base_idx]);
    __half2 h0 = *reinterpret_cast<__half2*>(&raw.x);
    __half2 h1 = *reinterpret_cast<__half2*>(&raw.y);
    float2 f0 = __half22float2(h0);
    float2 f1 = __half22float2(h1);
    x0 = f0.x; x1 = f0.y; x2 = f1.x; x3 = f1.y;
}

__global__ void gather_kernel(const float* __restrict__ gb,
                              const float* __restrict__ gamma,
                              const float* __restrict__ beta)
{
    __shared__ float shsum[64], shsq[64];
    if (threadIdx.x < 64) { shsum[threadIdx.x] = 0.0f; shsq[threadIdx.x] = 0.0f; }
    __syncthreads();

    int lane = threadIdx.x & 31;
    int half = lane >> 4;
    int l15  = lane & 15;
    int h    = l15 >> 2;
    int n = blockIdx.x * 8 + (threadIdx.x >> 5);
    {
        int beg = d_rowptr[n], end = d_rowptr[n + 1];
        float adh = __ldg(&d_ad[n * 4 + h]);

        float ax = 0.0f, ay = 0.0f, az = 0.0f, aw = 0.0f, ssum = 0.0f;
        if (half == 0) {
            // self loop: src = n
            float a = __ldg(&d_as[n * 4 + h]);
            float p = __expf(lrelu(a + adh));
            float x0, x1, x2, x3;
            load_xp4(n * 64 + 4 * l15, x0, x1, x2, x3);
            ssum = p;
            ax = x0 * p; ay = x1 * p; az = x2 * p; aw = x3 * p;
        }
        int i = beg + half;
        // batched: 4 edges per half-warp iteration, all loads issued before use
        for (; i + 6 < end; i += 8) {
            int s0 = __ldg(&d_csrc[i]);
            int s1 = __ldg(&d_csrc[i + 2]);
            int s2 = __ldg(&d_csrc[i + 4]);
            int s3 = __ldg(&d_csrc[i + 6]);
            float a0 = __ldg(&d_as[s0 * 4 + h]);
            float a1 = __ldg(&d_as[s1 * 4 + h]);
            float a2 = __ldg(&d_as[s2 * 4 + h]);
            float a3 = __ldg(&d_as[s3 * 4 + h]);
            uint2 r0 = *reinterpret_cast<const uint2*>(&d_xp[s0 * 64 + 4 * l15]);
            uint2 r1 = *reinterpret_cast<const uint2*>(&d_xp[s1 * 64 + 4 * l15]);
            uint2 r2 = *reinterpret_cast<const uint2*>(&d_xp[s2 * 64 + 4 * l15]);
            uint2 r3 = *reinterpret_cast<const uint2*>(&d_xp[s3 * 64 + 4 * l15]);
            float p0 = __expf(lrelu(a0 + adh));
            float p1 = __expf(lrelu(a1 + adh));
            float p2 = __expf(lrelu(a2 + adh));
            float p3 = __expf(lrelu(a3 + adh));
            {
                float2 f0 = __half22float2(*reinterpret_cast<__half2*>(&r0.x));
                float2 f1 = __half22float2(*reinterpret_cast<__half2*>(&r0.y));
                ssum += p0;
                ax = fmaf(f0.x, p0, ax); ay = fmaf(f0.y, p0, ay);
                az = fmaf(f1.x, p0, az); aw = fmaf(f1.y, p0, aw);
            }
            {
                float2 f0 = __half22float2(*reinterpret_cast<__half2*>(&r1.x));
                float2 f1 = __half22float2(*reinterpret_cast<__half2*>(&r1.y));
                ssum += p1;
                ax = fmaf(f0.x, p1, ax); ay = fmaf(f0.y, p1, ay);
                az = fmaf(f1.x, p1, az); aw = fmaf(f1.y, p1, aw);
            }
            {
                float2 f0 = __half22float2(*reinterpret_cast<__half2*>(&r2.x));
                float2 f1 = __half22float2(*reinterpret_cast<__half2*>(&r2.y));
                ssum += p2;
                ax = fmaf(f0.x, p2, ax); ay = fmaf(f0.y, p2, ay);
                az = fmaf(f1.x, p2, az); aw = fmaf(f1.y, p2, aw);
            }
            {
                float2 f0 = __half22float2(*reinterpret_cast<__half2*>(&r3.x));
                float2 f1 = __half22float2(*reinterpret_cast<__half2*>(&r3.y));
                ssum += p3;
                ax = fmaf(f0.x, p3, ax); ay = fmaf(f0.y, p3, ay);
                az = fmaf(f1.x, p3, az); aw = fmaf(f1.y, p3, aw);
            }
        }
        // remainder (0..3 edges per half)
        for (; i < end; i += 2) {
            int s = __ldg(&d_csrc[i]);
            float a = __ldg(&d_as[s * 4 + h]);
            float x0, x1, x2, x3;
            load_xp4(s * 64 + 4 * l15, x0, x1, x2, x3);
            float p = __expf(lrelu(a + adh));
            ssum += p;
            ax = fmaf(x0, p, ax);
            ay = fmaf(x1, p, ay);
            az = fmaf(x2, p, az);
            aw = fmaf(x3, p, aw);
        }
        // combine halves
        ssum += __shfl_xor_sync(0xffffffffu, ssum, 16);
        ax   += __shfl_xor_sync(0xffffffffu, ax, 16);
        ay   += __shfl_xor_sync(0xffffffffu, ay, 16);
        az   += __shfl_xor_sync(0xffffffffu, az, 16);
        aw   += __shfl_xor_sync(0xffffffffu, aw, 16);

        if (half == 0) {
            float inv = 1.0f / (ssum + 1e-16f);
            float4 gbv = *reinterpret_cast<const float4*>(&gb[4 * l15]);
            float v0 = ax * inv + gbv.x;
            float v1 = ay * inv + gbv.y;
            float v2 = az * inv + gbv.z;
            float v3 = aw * inv + gbv.w;
            *reinterpret_cast<float4*>(&d_h[n * 64 + 4 * l15]) = make_float4(v0, v1, v2, v3);
            int c = 4 * l15;
            atomicAdd(&shsum[c],     v0); atomicAdd(&shsq[c],     v0 * v0);
            atomicAdd(&shsum[c + 1], v1); atomicAdd(&shsq[c + 1], v1 * v1);
            atomicAdd(&shsum[c + 2], v2); atomicAdd(&shsq[c + 2], v2 * v2);
            atomicAdd(&shsum[c + 3], v3); atomicAdd(&shsq[c + 3], v3 * v3);
        }
    }
    __syncthreads();
    if (threadIdx.x < 64) {
        atomicAdd(&d_bn[threadIdx.x],      shsum[threadIdx.x]);
        atomicAdd(&d_bn[64 + threadIdx.x], shsq[threadIdx.x]);
    }

    // last-block: fold BN stats into scale/shift, reset d_bn + ticket
    __threadfence();
    __shared__ unsigned int isLast;
    if (threadIdx.x == 0)
        isLast = (atomicInc(&d_tick, 0xffffffffu) == gridDim.x - 1) ? 1u : 0u;
    __syncthreads();
    if (isLast) {
        int j = threadIdx.x;
        if (j < 64) {
            const float invN = 1.0f / (float)NN;
            float sum = atomicAdd(&d_bn[j], 0.0f);
            float sq  = atomicAdd(&d_bn[64 + j], 0.0f);
            float mu  = sum * invN;
            float var = sq * invN - mu * mu;
            float sc  = rsqrtf(var + 1e-5f) * __ldg(&gamma[j]);
            d_bnscale[j] = sc;
            d_bnshift[j] = __ldg(&beta[j]) - mu * sc;
            d_bn[j] = 0.0f; d_bn[64 + j] = 0.0f;
        }
        if (j == 64) d_tick = 0;
    }
}

// ---------------- pooling (applies last layer's BN+ELU) + MLP head ----------------
__global__ void pool_kernel(const int* __restrict__ batch) {
    int tid = threadIdx.x;
    int base = blockIdx.x * 128;
    int j4 = (tid & 15) * 4;
    int nlane = tid >> 4;
    float4 sc = *reinterpret_cast<const float4*>(&d_bnscale[j4]);
    float4 sh = *reinterpret_cast<const float4*>(&d_bnshift[j4]);
    float4 acc = make_float4(0.f, 0.f, 0.f, 0.f);
    int curb = -1;
    #pragma unroll
    for (int k = 0; k < 8; k++) {
        int n = base + nlane + 16 * k;
        if (n >= NN) break;
        int b = __ldg(&batch[n]);
        float4 hv = *reinterpret_cast<const float4*>(&d_h[n * 64 + j4]);
        float4 v;
        v.x = elu(fmaf(hv.x, sc.x, sh.x));
        v.y = elu(fmaf(hv.y, sc.y, sh.y));
        v.z = elu(fmaf(hv.z, sc.z, sh.z));
        v.w = elu(fmaf(hv.w, sc.w, sh.w));
        if (b != curb) {
            if (curb >= 0) {
                atomicAdd(&d_g[curb * 64 + j4],     acc.x);
                atomicAdd(&d_g[curb * 64 + j4 + 1], acc.y);
                atomicAdd(&d_g[curb * 64 + j4 + 2], acc.z);
                atomicAdd(&d_g[curb * 64 + j4 + 3], acc.w);
            }
            curb = b; acc = v;
        } else {
            acc.x += v.x; acc.y += v.y; acc.z += v.z; acc.w += v.w;
        }
    }
    if (curb >= 0) {
        atomicAdd(&d_g[curb * 64 + j4],     acc.x);
        atomicAdd(&d_g[curb * 64 + j4 + 1], acc.y);
        atomicAdd(&d_g[curb * 64 + j4 + 2], acc.z);
        atomicAdd(&d_g[curb * 64 + j4 + 3], acc.w);
    }
}

__global__ void head_kernel(const float* __restrict__ fc1W, const float* __restrict__ fc1b,
                            const float* __restrict__ fc2W, const float* __restrict__ fc2b,
                            float* __restrict__ out)
{
    __shared__ float gv[64];
    __shared__ float partial[2];
    int g = blockIdx.x, j = threadIdx.x;
    gv[j] = d_g[g * 64 + j];
    __syncthreads();
    float acc = __ldg(&fc1b[j]);
    #pragma unroll
    for (int k = 0; k < 64; k++) acc = fmaf(gv[k], __ldg(&fc1W[k * 64 + j]), acc);
    acc = fmaxf(acc, 0.0f) * __ldg(&fc2W[j]);
    #pragma unroll
    for (int off = 16; off; off >>= 1) acc += __shfl_xor_sync(0xffffffffu, acc, off);
    if ((j & 31) == 0) partial[j >> 5] = acc;
    __syncthreads();
    if (j == 0) out[g] = partial[0] + partial[1] + __ldg(&fc2b[0]);
}

// ---------------- launch ----------------
extern "C" void kernel_launch(void* const* d_in, const int* in_sizes, int n_in,
                              void* d_out, int out_size)
{
    const float* x     = (const float*)d_in[0];
    const float* embW  = (const float*)d_in[1];
    const float* embB  = (const float*)d_in[2];
    const float* gatW  = (const float*)d_in[3];
    const float* attS  = (const float*)d_in[4];
    const float* attD  = (const float*)d_in[5];
    const float* gatB  = (const float*)d_in[6];
    const float* bnG   = (const float*)d_in[7];
    const float* bnB   = (const float*)d_in[8];
    const float* fc1W  = (const float*)d_in[9];
    const float* fc1b  = (const float*)d_in[10];
    const float* fc2W  = (const float*)d_in[11];
    const float* fc2b  = (const float*)d_in[12];
    const int*   ei    = (const int*)d_in[13];
    const int*   batch = (const int*)d_in[14];
    float* out = (float*)d_out;

    void* p;
    cudaGetSymbolAddress(&p, d_h);  float*  h   = (float*)p;
    cudaGetSymbolAddress(&p, d_xp); __half* xp  = (__half*)p;
    cudaGetSymbolAddress(&p, d_as); float*  pas = (float*)p;
    cudaGetSymbolAddress(&p, d_ad); float*  pad = (float*)p;

    // side stream + fork/join events (created once, on the uncaptured correctness
    // call; graph topology is identical on every capture — work stays deterministic)
    static cudaStream_t s2 = nullptr;
    static cudaEvent_t evFork = nullptr, evJoin = nullptr;
    if (s2 == nullptr) {
        cudaStreamCreateWithFlags(&s2, cudaStreamNonBlocking);
        cudaEventCreateWithFlags(&evFork, cudaEventDisableTiming);
        cudaEventCreateWithFlags(&evJoin, cudaEventDisableTiming);
    }

    const int TB = 256;

    // fork: branch A (s2) builds CSR while branch B (legacy) runs the GEMMs
    cudaEventRecord(evFork, 0);
    cudaStreamWaitEvent(s2, evFork, 0);

    // --- branch A: CSR by dst (real edges only) ---
    hist_kernel<<<(EE / 2 + TB - 1) / TB, TB, 0, s2>>>(ei);
    scanA_kernel<<<SCAN_BLK, 1024, 0, s2>>>();
    scanC_kernel<<<(NN + TB - 1) / TB, TB, 0, s2>>>();
    scatter_kernel<<<(EE / 2 + TB - 1) / TB, TB, 0, s2>>>(ei);
    cudaEventRecord(evJoin, s2);

    // --- branch B: node embedding + layer-0 transform ---
    gemm2_kernel<128, 32><<<(NN + 31) / 32, 256>>>(x, embW, embB, h, NN);
    gemm4_kernel<64, 128, false><<<(NN + 127) / 128, 256>>>(
        h, gatW, attS, attD, xp, pas, pad, NN);

    // join: gather needs CSR + xp/as/ad
    cudaStreamWaitEvent(0, evJoin, 0);

    gather_kernel<<<NN / 8, 256>>>(gatB, bnG, bnB);

    // layers 1..3 (prev layer's BN+ELU fused into GEMM X-load)
    for (int l = 1; l < NLAYERS; l++) {
        gemm4_kernel<64, 128, true><<<(NN + 127) / 128, 256>>>(
            h, gatW + l * 64 * 64, attS + l * 64, attD + l * 64,
            xp, pas, pad, NN);
        gather_kernel<<<NN / 8, 256>>>(gatB + l * 64, bnG + l * 64, bnB + l * 64);
    }

    // pool (applies layer-3 BN+ELU) + head
    pool_kernel<<<(NN + 127) / 128, 256>>>(batch);
    head_kernel<<<GG, 64>>>(fc1W, fc1b, fc2W, fc2b, out);
}

// round 17
// speedup vs baseline: 1.3674x; 1.1435x over previous
#include <cuda_runtime.h>
#include <cuda_fp16.h>
#include <math.h>

#define NN 50000
#define EE 800000
#define GG 256
#define NLAYERS 4
#define SCAN_BLK ((NN + 1023) / 1024)   // 49
#define GATHER_BLOCKS 592               // 4 blocks/SM on 148 SMs, 4736 warps
#define GATHER_WARPS (GATHER_BLOCKS * 8)

// ---------------- static device scratch ----------------
__device__ __align__(16) float  d_h [NN * 64];
__device__ __align__(16) __half d_xp[NN * 64];   // fp16 messages
__device__ __align__(16) float  d_as[NN * 4];
__device__ __align__(16) float  d_ad[NN * 4];
__device__ int   d_cnt[NN];          // kept zeroed between calls
__device__ int   d_rowptr[NN + 1];
__device__ int   d_cursor[NN];
__device__ int   d_bsum[SCAN_BLK];
__device__ int   d_csrc[EE];         // real edges only; self-loops handled inline
__device__ float d_bn[128];          // kept zeroed between calls
__device__ __align__(16) float d_bnscale[64];
__device__ __align__(16) float d_bnshift[64];
__device__ float d_g [GG * 64];
__device__ unsigned int d_tick;      // last-block ticket (kept zeroed)

__device__ __forceinline__ float lrelu(float x) { return x > 0.0f ? x : 0.2f * x; }
__device__ __forceinline__ float elu(float x)   { return x > 0.0f ? x : expm1f(x); }

// ---------------- CSR build ----------------
__global__ void hist_kernel(const int* __restrict__ ei) {
    int i0 = (blockIdx.x * blockDim.x + threadIdx.x) * 2;
    if (i0 < EE) {
        int2 dd = *reinterpret_cast<const int2*>(&ei[EE + i0]);   // EE even, i0 even -> aligned
        atomicAdd(&d_cnt[dd.x], 1);
        atomicAdd(&d_cnt[dd.y], 1);
    }
}

// block-local exclusive scan (1024/block)
__global__ void scanA_kernel() {
    __shared__ int wsum[32];
    int i = blockIdx.x * 1024 + threadIdx.x;
    int lane = threadIdx.x & 31, warp = threadIdx.x >> 5;
    int v = (i < NN) ? d_cnt[i] : 0;
    int orig = v;
    #pragma unroll
    for (int off = 1; off < 32; off <<= 1) {
        int t = __shfl_up_sync(0xffffffffu, v, off);
        if (lane >= off) v += t;
    }
    if (lane == 31) wsum[warp] = v;
    __syncthreads();
    if (threadIdx.x < 32) {
        int w = wsum[threadIdx.x];
        #pragma unroll
        for (int off = 1; off < 32; off <<= 1) {
            int t = __shfl_up_sync(0xffffffffu, w, off);
            if (lane >= off) w += t;
        }
        wsum[threadIdx.x] = w;
    }
    __syncthreads();
    int prefix = warp ? wsum[warp - 1] : 0;
    int incl = v + prefix;
    if (i < NN) d_rowptr[i] = incl - orig;
    if (threadIdx.x == 1023) d_bsum[blockIdx.x] = incl;
}

// fused: block-prefix (inline), cursor copy, cnt reset, zero d_g, rowptr[NN]
__global__ void scanC_kernel() {
    int i = blockIdx.x * blockDim.x + threadIdx.x;
    if (i < NN) {
        int blk = i >> 10;
        int prefix = 0;
        for (int b = 0; b < blk; b++) prefix += __ldg(&d_bsum[b]);
        int r = d_rowptr[i] + prefix;
        d_rowptr[i] = r;
        d_cursor[i] = r;
        d_cnt[i] = 0;
    }
    if (i == 0) d_rowptr[NN] = EE;
    if (i < GG * 64) d_g[i] = 0.0f;
}

__global__ void scatter_kernel(const int* __restrict__ ei) {
    int i0 = (blockIdx.x * blockDim.x + threadIdx.x) * 2;
    if (i0 < EE) {
        int2 dd = *reinterpret_cast<const int2*>(&ei[EE + i0]);
        int2 ss = *reinterpret_cast<const int2*>(&ei[i0]);
        int p0 = atomicAdd(&d_cursor[dd.x], 1);
        int p1 = atomicAdd(&d_cursor[dd.y], 1);
        d_csrc[p0] = ss.x;
        d_csrc[p1] = ss.y;
    }
}

// ---------------- embed GEMM: X[nrows,128] @ W[128,64] + bias ----------------
template<int K, int NB>
__global__ void gemm2_kernel(const float* __restrict__ X, const float* __restrict__ W,
                             const float* __restrict__ bias, float* __restrict__ out,
                             int nrows)
{
    constexpr int U = NB / 8;
    constexpr int KQ = K / 4;
    __shared__ float Wsh[K * 64];
    __shared__ float Xsh[NB * K];
    int tid = threadIdx.x;
    for (int i = tid; i < K * 16; i += 256)
        reinterpret_cast<float4*>(Wsh)[i] = __ldg(&reinterpret_cast<const float4*>(W)[i]);
    int nb = blockIdx.x * NB;
    for (int i = tid; i < NB * KQ; i += 256) {
        int r = i / KQ, kq = i - r * KQ;
        int row = nb + r;
        float4 v = make_float4(0.f, 0.f, 0.f, 0.f);
        if (row < nrows) v = __ldg(&reinterpret_cast<const float4*>(X)[row * KQ + kq]);
        reinterpret_cast<float4*>(Xsh)[i] = v;
    }
    __syncthreads();

    int lane = tid & 31;
    int jp   = lane * 2;
    int r0   = tid >> 5;
    float acc0[U], acc1[U];
    #pragma unroll
    for (int u = 0; u < U; u++) { acc0[u] = 0.0f; acc1[u] = 0.0f; }

    #pragma unroll 4
    for (int k = 0; k < K; k++) {
        float2 w = *reinterpret_cast<const float2*>(&Wsh[k * 64 + jp]);
        #pragma unroll
        for (int u = 0; u < U; u++) {
            float xv = Xsh[(r0 + 8 * u) * K + k];
            acc0[u] = fmaf(xv, w.x, acc0[u]);
            acc1[u] = fmaf(xv, w.y, acc1[u]);
        }
    }
    float b0 = __ldg(&bias[jp]), b1 = __ldg(&bias[jp + 1]);
    #pragma unroll
    for (int u = 0; u < U; u++) {
        int row = nb + r0 + 8 * u;
        if (row < nrows)
            *reinterpret_cast<float2*>(&out[row * 64 + jp]) = make_float2(acc0[u] + b0, acc1[u] + b1);
    }
}

// ---------------- layer GEMM: h[N,64] @ W[64,64] -> xp (fp16), + attention logits ----------------
template<int K, int NB, bool BNF>
__global__ void gemm4_kernel(const float* __restrict__ X, const float* __restrict__ W,
                             const float* __restrict__ attS, const float* __restrict__ attD,
                             __half* __restrict__ out,
                             float* __restrict__ asOut, float* __restrict__ adOut,
                             int nrows)
{
    constexpr int U = NB / 16;
    constexpr int KQ = K / 4;
    __shared__ float Wsh[K * 64];
    __shared__ float Xsh[NB * K];
    int tid = threadIdx.x;
    for (int i = tid; i < K * 16; i += 256)
        reinterpret_cast<float4*>(Wsh)[i] = __ldg(&reinterpret_cast<const float4*>(W)[i]);
    int nb = blockIdx.x * NB;
    for (int i = tid; i < NB * KQ; i += 256) {
        int r = i / KQ, kq = i - r * KQ;
        int row = nb + r;
        float4 v = make_float4(0.f, 0.f, 0.f, 0.f);
        if (row < nrows) v = __ldg(&reinterpret_cast<const float4*>(X)[row * KQ + kq]);
        if (BNF) {
            float4 sc = *reinterpret_cast<const float4*>(&d_bnscale[kq * 4]);  // K==64 when BNF
            float4 sh = *reinterpret_cast<const float4*>(&d_bnshift[kq * 4]);
            v.x = elu(fmaf(v.x, sc.x, sh.x));
            v.y = elu(fmaf(v.y, sc.y, sh.y));
            v.z = elu(fmaf(v.z, sc.z, sh.z));
            v.w = elu(fmaf(v.w, sc.w, sh.w));
        }
        reinterpret_cast<float4*>(Xsh)[i] = v;
    }
    __syncthreads();

    int lane = tid & 31;
    int cs = tid & 15, rs = tid >> 4;
    int j4 = cs * 4;
    float acc[U][4];
    #pragma unroll
    for (int u = 0; u < U; u++)
        #pragma unroll
        for (int c = 0; c < 4; c++) acc[u][c] = 0.0f;

    #pragma unroll 4
    for (int k = 0; k < K; k++) {
        float4 w = *reinterpret_cast<const float4*>(&Wsh[k * 64 + j4]);
        #pragma unroll
        for (int u = 0; u < U; u++) {
            float xv = Xsh[(rs + 16 * u) * K + k];
            acc[u][0] = fmaf(xv, w.x, acc[u][0]);
            acc[u][1] = fmaf(xv, w.y, acc[u][1]);
            acc[u][2] = fmaf(xv, w.z, acc[u][2]);
            acc[u][3] = fmaf(xv, w.w, acc[u][3]);
        }
    }

    float4 es = *reinterpret_cast<const float4*>(&attS[j4]);
    float4 ed = *reinterpret_cast<const float4*>(&attD[j4]);
    int head = cs >> 2;

    #pragma unroll
    for (int u = 0; u < U; u++) {
        int row = nb + rs + 16 * u;
        float4 v = make_float4(acc[u][0], acc[u][1], acc[u][2], acc[u][3]);
        if (row < nrows) {
            __half2 p0 = __float22half2_rn(make_float2(v.x, v.y));
            __half2 p1 = __float22half2_rn(make_float2(v.z, v.w));
            uint2 st;
            st.x = *reinterpret_cast<unsigned int*>(&p0);
            st.y = *reinterpret_cast<unsigned int*>(&p1);
            *reinterpret_cast<uint2*>(&out[row * 64 + j4]) = st;
        }
        float vs = v.x * es.x + v.y * es.y + v.z * es.z + v.w * es.w;
        float vd = v.x * ed.x + v.y * ed.y + v.z * ed.z + v.w * ed.w;
        vs += __shfl_xor_sync(0xffffffffu, vs, 1);
        vd += __shfl_xor_sync(0xffffffffu, vd, 1);
        vs += __shfl_xor_sync(0xffffffffu, vs, 2);
        vd += __shfl_xor_sync(0xffffffffu, vd, 2);
        if ((lane & 3) == 0 && row < nrows) {
            asOut[row * 4 + head] = vs;
            adOut[row * 4 + head] = vd;
        }
    }
}

// ---------------- attention gather: multi-node per warp, register BN partials ----------------
__device__ __forceinline__ void load_xp4(int base_idx, float& x0, float& x1, float& x2, float& x3) {
    uint2 raw = *reinterpret_cast<const uint2*>(&d_xp[base_idx]);
    __half2 h0 = *reinterpret_cast<__half2*>(&raw.x);
    __half2 h1 = *reinterpret_cast<__half2*>(&raw.y);
    float2 f0 = __half22float2(h0);
    float2 f1 = __half22float2(h1);
    x0 = f0.x; x1 = f0.y; x2 = f1.x; x3 = f1.y;
}

__global__ void gather_kernel(const float* __restrict__ gb,
                              const float* __restrict__ gamma,
                              const float* __restrict__ beta)
{
    __shared__ float shsum[64], shsq[64];
    if (threadIdx.x < 64) { shsum[threadIdx.x] = 0.0f; shsq[threadIdx.x] = 0.0f; }
    __syncthreads();

    int lane = threadIdx.x & 31;
    int half = lane >> 4;
    int l15  = lane & 15;
    int h    = l15 >> 2;
    int warpG = blockIdx.x * 8 + (threadIdx.x >> 5);

    // BN partials for this warp's owned channels (half-0 lanes), kept in registers
    float bns0 = 0.f, bns1 = 0.f, bns2 = 0.f, bns3 = 0.f;
    float bnq0 = 0.f, bnq1 = 0.f, bnq2 = 0.f, bnq3 = 0.f;
    float4 gbv = *reinterpret_cast<const float4*>(&gb[4 * l15]);

    for (int n = warpG; n < NN; n += GATHER_WARPS) {
        int beg = d_rowptr[n], end = d_rowptr[n + 1];
        float adh = __ldg(&d_ad[n * 4 + h]);

        float ax = 0.0f, ay = 0.0f, az = 0.0f, aw = 0.0f, ssum = 0.0f;
        if (half == 0) {
            // self loop: src = n
            float a = __ldg(&d_as[n * 4 + h]);
            float p = __expf(lrelu(a + adh));
            float x0, x1, x2, x3;
            load_xp4(n * 64 + 4 * l15, x0, x1, x2, x3);
            ssum = p;
            ax = x0 * p; ay = x1 * p; az = x2 * p; aw = x3 * p;
        }
        int i = beg + half;
        // batched: 4 edges per half-warp iteration, all loads issued before use
        for (; i + 6 < end; i += 8) {
            int s0 = __ldg(&d_csrc[i]);
            int s1 = __ldg(&d_csrc[i + 2]);
            int s2 = __ldg(&d_csrc[i + 4]);
            int s3 = __ldg(&d_csrc[i + 6]);
            float a0 = __ldg(&d_as[s0 * 4 + h]);
            float a1 = __ldg(&d_as[s1 * 4 + h]);
            float a2 = __ldg(&d_as[s2 * 4 + h]);
            float a3 = __ldg(&d_as[s3 * 4 + h]);
            uint2 r0 = *reinterpret_cast<const uint2*>(&d_xp[s0 * 64 + 4 * l15]);
            uint2 r1 = *reinterpret_cast<const uint2*>(&d_xp[s1 * 64 + 4 * l15]);
            uint2 r2 = *reinterpret_cast<const uint2*>(&d_xp[s2 * 64 + 4 * l15]);
            uint2 r3 = *reinterpret_cast<const uint2*>(&d_xp[s3 * 64 + 4 * l15]);
            float p0 = __expf(lrelu(a0 + adh));
            float p1 = __expf(lrelu(a1 + adh));
            float p2 = __expf(lrelu(a2 + adh));
            float p3 = __expf(lrelu(a3 + adh));
            {
                float2 f0 = __half22float2(*reinterpret_cast<__half2*>(&r0.x));
                float2 f1 = __half22float2(*reinterpret_cast<__half2*>(&r0.y));
                ssum += p0;
                ax = fmaf(f0.x, p0, ax); ay = fmaf(f0.y, p0, ay);
                az = fmaf(f1.x, p0, az); aw = fmaf(f1.y, p0, aw);
            }
            {
                float2 f0 = __half22float2(*reinterpret_cast<__half2*>(&r1.x));
                float2 f1 = __half22float2(*reinterpret_cast<__half2*>(&r1.y));
                ssum += p1;
                ax = fmaf(f0.x, p1, ax); ay = fmaf(f0.y, p1, ay);
                az = fmaf(f1.x, p1, az); aw = fmaf(f1.y, p1, aw);
            }
            {
                float2 f0 = __half22float2(*reinterpret_cast<__half2*>(&r2.x));
                float2 f1 = __half22float2(*reinterpret_cast<__half2*>(&r2.y));
                ssum += p2;
                ax = fmaf(f0.x, p2, ax); ay = fmaf(f0.y, p2, ay);
                az = fmaf(f1.x, p2, az); aw = fmaf(f1.y, p2, aw);
            }
            {
                float2 f0 = __half22float2(*reinterpret_cast<__half2*>(&r3.x));
                float2 f1 = __half22float2(*reinterpret_cast<__half2*>(&r3.y));
                ssum += p3;
                ax = fmaf(f0.x, p3, ax); ay = fmaf(f0.y, p3, ay);
                az = fmaf(f1.x, p3, az); aw = fmaf(f1.y, p3, aw);
            }
        }
        // remainder (0..3 edges per half)
        for (; i < end; i += 2) {
            int s = __ldg(&d_csrc[i]);
            float a = __ldg(&d_as[s * 4 + h]);
            float x0, x1, x2, x3;
            load_xp4(s * 64 + 4 * l15, x0, x1, x2, x3);
            float p = __expf(lrelu(a + adh));
            ssum += p;
            ax = fmaf(x0, p, ax);
            ay = fmaf(x1, p, ay);
            az = fmaf(x2, p, az);
            aw = fmaf(x3, p, aw);
        }
        // combine halves
        ssum += __shfl_xor_sync(0xffffffffu, ssum, 16);
        ax   += __shfl_xor_sync(0xffffffffu, ax, 16);
        ay   += __shfl_xor_sync(0xffffffffu, ay, 16);
        az   += __shfl_xor_sync(0xffffffffu, az, 16);
        aw   += __shfl_xor_sync(0xffffffffu, aw, 16);

        if (half == 0) {
            float inv = 1.0f / (ssum + 1e-16f);
            float v0 = ax * inv + gbv.x;
            float v1 = ay * inv + gbv.y;
            float v2 = az * inv + gbv.z;
            float v3 = aw * inv + gbv.w;
            *reinterpret_cast<float4*>(&d_h[n * 64 + 4 * l15]) = make_float4(v0, v1, v2, v3);
            bns0 += v0; bnq0 += v0 * v0;
            bns1 += v1; bnq1 += v1 * v1;
            bns2 += v2; bnq2 += v2 * v2;
            bns3 += v3; bnq3 += v3 * v3;
        }
    }

    // per-warp BN flush (once), then block flush to global
    if (half == 0) {
        int c = 4 * l15;
        atomicAdd(&shsum[c],     bns0); atomicAdd(&shsq[c],     bnq0);
        atomicAdd(&shsum[c + 1], bns1); atomicAdd(&shsq[c + 1], bnq1);
        atomicAdd(&shsum[c + 2], bns2); atomicAdd(&shsq[c + 2], bnq2);
        atomicAdd(&shsum[c + 3], bns3); atomicAdd(&shsq[c + 3], bnq3);
    }
    __syncthreads();
    if (threadIdx.x < 64) {
        atomicAdd(&d_bn[threadIdx.x],      shsum[threadIdx.x]);
        atomicAdd(&d_bn[64 + threadIdx.x], shsq[threadIdx.x]);
    }

    // last-block: fold BN stats into scale/shift, reset d_bn + ticket
    __threadfence();
    __shared__ unsigned int isLast;
    if (threadIdx.x == 0)
        isLast = (atomicInc(&d_tick, 0xffffffffu) == gridDim.x - 1) ? 1u : 0u;
    __syncthreads();
    if (isLast) {
        int j = threadIdx.x;
        if (j < 64) {
            const float invN = 1.0f / (float)NN;
            float sum = atomicAdd(&d_bn[j], 0.0f);
            float sq  = atomicAdd(&d_bn[64 + j], 0.0f);
            float mu  = sum * invN;
            float var = sq * invN - mu * mu;
            float sc  = rsqrtf(var + 1e-5f) * __ldg(&gamma[j]);
            d_bnscale[j] = sc;
            d_bnshift[j] = __ldg(&beta[j]) - mu * sc;
            d_bn[j] = 0.0f; d_bn[64 + j] = 0.0f;
        }
        if (j == 64) d_tick = 0;
    }
}

// ---------------- pooling (applies last layer's BN+ELU) + MLP head ----------------
__global__ void pool_kernel(const int* __restrict__ batch) {
    int tid = threadIdx.x;
    int base = blockIdx.x * 128;
    int j4 = (tid & 15) * 4;
    int nlane = tid >> 4;
    float4 sc = *reinterpret_cast<const float4*>(&d_bnscale[j4]);
    float4 sh = *reinterpret_cast<const float4*>(&d_bnshift[j4]);
    float4 acc = make_float4(0.f, 0.f, 0.f, 0.f);
    int curb = -1;
    #pragma unroll
    for (int k = 0; k < 8; k++) {
        int n = base + nlane + 16 * k;
        if (n >= NN) break;
        int b = __ldg(&batch[n]);
        float4 hv = *reinterpret_cast<const float4*>(&d_h[n * 64 + j4]);
        float4 v;
        v.x = elu(fmaf(hv.x, sc.x, sh.x));
        v.y = elu(fmaf(hv.y, sc.y, sh.y));
        v.z = elu(fmaf(hv.z, sc.z, sh.z));
        v.w = elu(fmaf(hv.w, sc.w, sh.w));
        if (b != curb) {
            if (curb >= 0) {
                atomicAdd(&d_g[curb * 64 + j4],     acc.x);
                atomicAdd(&d_g[curb * 64 + j4 + 1], acc.y);
                atomicAdd(&d_g[curb * 64 + j4 + 2], acc.z);
                atomicAdd(&d_g[curb * 64 + j4 + 3], acc.w);
            }
            curb = b; acc = v;
        } else {
            acc.x += v.x; acc.y += v.y; acc.z += v.z; acc.w += v.w;
        }
    }
    if (curb >= 0) {
        atomicAdd(&d_g[curb * 64 + j4],     acc.x);
        atomicAdd(&d_g[curb * 64 + j4 + 1], acc.y);
        atomicAdd(&d_g[curb * 64 + j4 + 2], acc.z);
        atomicAdd(&d_g[curb * 64 + j4 + 3], acc.w);
    }
}

__global__ void head_kernel(const float* __restrict__ fc1W, const float* __restrict__ fc1b,
                            const float* __restrict__ fc2W, const float* __restrict__ fc2b,
                            float* __restrict__ out)
{
    __shared__ float gv[64];
    __shared__ float partial[2];
    int g = blockIdx.x, j = threadIdx.x;
    gv[j] = d_g[g * 64 + j];
    __syncthreads();
    float acc = __ldg(&fc1b[j]);
    #pragma unroll
    for (int k = 0; k < 64; k++) acc = fmaf(gv[k], __ldg(&fc1W[k * 64 + j]), acc);
    acc = fmaxf(acc, 0.0f) * __ldg(&fc2W[j]);
    #pragma unroll
    for (int off = 16; off; off >>= 1) acc += __shfl_xor_sync(0xffffffffu, acc, off);
    if ((j & 31) == 0) partial[j >> 5] = acc;
    __syncthreads();
    if (j == 0) out[g] = partial[0] + partial[1] + __ldg(&fc2b[0]);
}

// ---------------- launch ----------------
extern "C" void kernel_launch(void* const* d_in, const int* in_sizes, int n_in,
                              void* d_out, int out_size)
{
    const float* x     = (const float*)d_in[0];
    const float* embW  = (const float*)d_in[1];
    const float* embB  = (const float*)d_in[2];
    const float* gatW  = (const float*)d_in[3];
    const float* attS  = (const float*)d_in[4];
    const float* attD  = (const float*)d_in[5];
    const float* gatB  = (const float*)d_in[6];
    const float* bnG   = (const float*)d_in[7];
    const float* bnB   = (const float*)d_in[8];
    const float* fc1W  = (const float*)d_in[9];
    const float* fc1b  = (const float*)d_in[10];
    const float* fc2W  = (const float*)d_in[11];
    const float* fc2b  = (const float*)d_in[12];
    const int*   ei    = (const int*)d_in[13];
    const int*   batch = (const int*)d_in[14];
    float* out = (float*)d_out;

    void* p;
    cudaGetSymbolAddress(&p, d_h);  float*  h   = (float*)p;
    cudaGetSymbolAddress(&p, d_xp); __half* xp  = (__half*)p;
    cudaGetSymbolAddress(&p, d_as); float*  pas = (float*)p;
    cudaGetSymbolAddress(&p, d_ad); float*  pad = (float*)p;

    // side stream + fork/join events (created once, on the uncaptured correctness
    // call; graph topology is identical on every capture — work stays deterministic)
    static cudaStream_t s2 = nullptr;
    static cudaEvent_t evFork = nullptr, evJoin = nullptr;
    if (s2 == nullptr) {
        cudaStreamCreateWithFlags(&s2, cudaStreamNonBlocking);
        cudaEventCreateWithFlags(&evFork, cudaEventDisableTiming);
        cudaEventCreateWithFlags(&evJoin, cudaEventDisableTiming);
    }

    const int TB = 256;

    // fork: branch A (s2) builds CSR while branch B (legacy) runs the GEMMs
    cudaEventRecord(evFork, 0);
    cudaStreamWaitEvent(s2, evFork, 0);

    // --- branch A: CSR by dst (real edges only) ---
    hist_kernel<<<(EE / 2 + TB - 1) / TB, TB, 0, s2>>>(ei);
    scanA_kernel<<<SCAN_BLK, 1024, 0, s2>>>();
    scanC_kernel<<<(NN + TB - 1) / TB, TB, 0, s2>>>();
    scatter_kernel<<<(EE / 2 + TB - 1) / TB, TB, 0, s2>>>(ei);
    cudaEventRecord(evJoin, s2);

    // --- branch B: node embedding + layer-0 transform ---
    gemm2_kernel<128, 32><<<(NN + 31) / 32, 256>>>(x, embW, embB, h, NN);
    gemm4_kernel<64, 128, false><<<(NN + 127) / 128, 256>>>(
        h, gatW, attS, attD, xp, pas, pad, NN);

    // join: gather needs CSR + xp/as/ad
    cudaStreamWaitEvent(0, evJoin, 0);

    gather_kernel<<<GATHER_BLOCKS, 256>>>(gatB, bnG, bnB);

    // layers 1..3 (prev layer's BN+ELU fused into GEMM X-load)
    for (int l = 1; l < NLAYERS; l++) {
        gemm4_kernel<64, 128, true><<<(NN + 127) / 128, 256>>>(
            h, gatW + l * 64 * 64, attS + l * 64, attD + l * 64,
            xp, pas, pad, NN);
        gather_kernel<<<GATHER_BLOCKS, 256>>>(gatB + l * 64, bnG + l * 64, bnB + l * 64);
    }

    // pool (applies layer-3 BN+ELU) + head
    pool_kernel<<<(NN + 127) / 128, 256>>>(batch);
    head_kernel<<<GG, 64>>>(fc1W, fc1b, fc2W, fc2b, out);
}